// round 1
// baseline (speedup 1.0000x reference)
#include <cuda_runtime.h>

#define N_NODES   65536
#define NUM_TYPES 64
#define DIM       240

// ---- scratch (no allocs allowed) ----
__device__ int g_counts[NUM_TYPES];
__device__ int g_bases[NUM_TYPES];
__device__ int g_cursor[NUM_TYPES];
__device__ int g_perm[N_NODES];

// ---------------------------------------------------------------------------
// Counting sort by type: zero -> histogram -> scan -> scatter
// ---------------------------------------------------------------------------
__global__ void k_zero() {
    g_counts[threadIdx.x] = 0;
}

__global__ void k_hist(const int* __restrict__ idx) {
    __shared__ int h[NUM_TYPES];
    if (threadIdx.x < NUM_TYPES) h[threadIdx.x] = 0;
    __syncthreads();
    int i = blockIdx.x * blockDim.x + threadIdx.x;
    atomicAdd(&h[idx[i]], 1);
    __syncthreads();
    if (threadIdx.x < NUM_TYPES) atomicAdd(&g_counts[threadIdx.x], h[threadIdx.x]);
}

__global__ void k_scan() {
    int s = 0;
    for (int t = 0; t < NUM_TYPES; t++) {
        g_bases[t] = s;
        g_cursor[t] = s;
        s += g_counts[t];
    }
}

__global__ void k_scatter(const int* __restrict__ idx) {
    int i = blockIdx.x * blockDim.x + threadIdx.x;
    int t = idx[i];
    unsigned mask = __match_any_sync(0xffffffffu, t);
    int lane = threadIdx.x & 31;
    int leader = __ffs(mask) - 1;
    int rank = __popc(mask & ((1u << lane) - 1));
    int pos = 0;
    if (lane == leader) pos = atomicAdd(&g_cursor[t], __popc(mask));
    pos = __shfl_sync(0xffffffffu, pos, leader);
    g_perm[pos + rank] = i;
}

// ---------------------------------------------------------------------------
// Main kernel: grid = 64 types x 8 chunks, 128 threads (4 warps) per block.
// Block loads its type's (prescaled) weights to SMEM once; each warp handles
// groups of 32 nodes (one node per lane). Weight reads are warp-uniform SMEM
// broadcasts via LDS.128.
// ---------------------------------------------------------------------------
#define KBLK 8  // blocks per type

__global__ __launch_bounds__(128) void k_main(
    const float* __restrict__ x,
    const float* __restrict__ W0,
    const float* __restrict__ W1,
    const float* __restrict__ W2,
    float* __restrict__ out)
{
    __shared__ float sW0[64 * 64];
    __shared__ float sW1[32 * 32];
    __shared__ float sW2[16 * 16];

    const int t   = blockIdx.x & (NUM_TYPES - 1);
    const int k   = blockIdx.x >> 6;          // 0..KBLK-1
    const int tid = threadIdx.x;

    // load + prescale weights (scale folded in => compute loop is pure FMA)
    {
        const float s0 = 0.125f;                 // 1/sqrt(64)
        const float s1 = 0.17677669529663687f;   // 1/sqrt(32)
        const float s2 = 0.25f;                  // 1/sqrt(16)

        const float4* w0 = (const float4*)(W0 + (size_t)t * 4096);
        float4* p0 = (float4*)sW0;
        for (int i = tid; i < 1024; i += 128) {
            float4 v = w0[i];
            v.x *= s0; v.y *= s0; v.z *= s0; v.w *= s0;
            p0[i] = v;
        }
        const float4* w1 = (const float4*)(W1 + (size_t)t * 1024);
        float4* p1 = (float4*)sW1;
        for (int i = tid; i < 256; i += 128) {
            float4 v = w1[i];
            v.x *= s1; v.y *= s1; v.z *= s1; v.w *= s1;
            p1[i] = v;
        }
        const float4* w2 = (const float4*)(W2 + (size_t)t * 256);
        float4* p2 = (float4*)sW2;
        for (int i = tid; i < 64; i += 128) {
            float4 v = w2[i];
            v.x *= s2; v.y *= s2; v.z *= s2; v.w *= s2;
            p2[i] = v;
        }
    }

    const int cnt  = g_counts[t];
    const int base = g_bases[t];
    __syncthreads();

    const int warp = tid >> 5;
    const int lane = tid & 31;
    const int ngroups = (cnt + 31) >> 5;

    for (int g = k * 4 + warp; g < ngroups; g += KBLK * 4) {
        const int j = g * 32 + lane;
        const bool valid = (j < cnt);
        const int jj = valid ? j : (cnt - 1);   // cnt >= 1 guaranteed here
        const int node = g_perm[base + jj];
        const float* xr  = x   + (size_t)node * DIM;
        float*       orow = out + (size_t)node * DIM;

        // ================= irrep 0: m=64, d=1 =================
        {
            float x0[64];
            const float4* xv = (const float4*)xr;
            #pragma unroll
            for (int v = 0; v < 16; v++) {
                float4 q = xv[v];
                x0[4*v+0] = q.x; x0[4*v+1] = q.y; x0[4*v+2] = q.z; x0[4*v+3] = q.w;
            }
            #pragma unroll 1
            for (int og = 0; og < 8; og++) {
                float a0=0.f,a1=0.f,a2=0.f,a3=0.f,a4=0.f,a5=0.f,a6=0.f,a7=0.f;
                const float4* wp = (const float4*)&sW0[og * 8]; // + i*16 per row
                #pragma unroll
                for (int i = 0; i < 64; i++) {
                    float4 wA = wp[i * 16];
                    float4 wB = wp[i * 16 + 1];
                    float xi = x0[i];
                    a0 = fmaf(xi, wA.x, a0); a1 = fmaf(xi, wA.y, a1);
                    a2 = fmaf(xi, wA.z, a2); a3 = fmaf(xi, wA.w, a3);
                    a4 = fmaf(xi, wB.x, a4); a5 = fmaf(xi, wB.y, a5);
                    a6 = fmaf(xi, wB.z, a6); a7 = fmaf(xi, wB.w, a7);
                }
                if (valid) {
                    ((float4*)orow)[og * 2 + 0] = make_float4(a0, a1, a2, a3);
                    ((float4*)orow)[og * 2 + 1] = make_float4(a4, a5, a6, a7);
                }
            }
        }

        // ================= irrep 1: m=32, d=3 =================
        {
            float x1r[96];
            const float4* xv = (const float4*)(xr + 64);
            #pragma unroll
            for (int v = 0; v < 24; v++) {
                float4 q = xv[v];
                x1r[4*v+0] = q.x; x1r[4*v+1] = q.y; x1r[4*v+2] = q.z; x1r[4*v+3] = q.w;
            }
            #pragma unroll 1
            for (int og = 0; og < 8; og++) {
                float a[12];
                #pragma unroll
                for (int q = 0; q < 12; q++) a[q] = 0.f;
                const float4* wp = (const float4*)&sW1[og * 4]; // + i*8 per row
                #pragma unroll
                for (int i = 0; i < 32; i++) {
                    float4 w = wp[i * 8];
                    float b0 = x1r[3*i], b1 = x1r[3*i+1], b2 = x1r[3*i+2];
                    a[0]  = fmaf(w.x, b0, a[0]);  a[1]  = fmaf(w.x, b1, a[1]);  a[2]  = fmaf(w.x, b2, a[2]);
                    a[3]  = fmaf(w.y, b0, a[3]);  a[4]  = fmaf(w.y, b1, a[4]);  a[5]  = fmaf(w.y, b2, a[5]);
                    a[6]  = fmaf(w.z, b0, a[6]);  a[7]  = fmaf(w.z, b1, a[7]);  a[8]  = fmaf(w.z, b2, a[8]);
                    a[9]  = fmaf(w.w, b0, a[9]);  a[10] = fmaf(w.w, b1, a[10]); a[11] = fmaf(w.w, b2, a[11]);
                }
                if (valid) {
                    float2* o2 = (float2*)(orow + 64 + og * 12);  // 8B aligned always
                    o2[0] = make_float2(a[0],  a[1]);
                    o2[1] = make_float2(a[2],  a[3]);
                    o2[2] = make_float2(a[4],  a[5]);
                    o2[3] = make_float2(a[6],  a[7]);
                    o2[4] = make_float2(a[8],  a[9]);
                    o2[5] = make_float2(a[10], a[11]);
                }
            }
        }

        // ================= irrep 2: m=16, d=5 =================
        {
            float x2r[80];
            const float4* xv = (const float4*)(xr + 160);
            #pragma unroll
            for (int v = 0; v < 20; v++) {
                float4 q = xv[v];
                x2r[4*v+0] = q.x; x2r[4*v+1] = q.y; x2r[4*v+2] = q.z; x2r[4*v+3] = q.w;
            }
            #pragma unroll 1
            for (int og = 0; og < 4; og++) {
                float a[20];
                #pragma unroll
                for (int q = 0; q < 20; q++) a[q] = 0.f;
                const float4* wp = (const float4*)&sW2[og * 4]; // + i*4 per row
                #pragma unroll
                for (int i = 0; i < 16; i++) {
                    float4 w = wp[i * 4];
                    float b0 = x2r[5*i], b1 = x2r[5*i+1], b2 = x2r[5*i+2],
                          b3 = x2r[5*i+3], b4 = x2r[5*i+4];
                    a[0]  = fmaf(w.x, b0, a[0]);  a[1]  = fmaf(w.x, b1, a[1]);
                    a[2]  = fmaf(w.x, b2, a[2]);  a[3]  = fmaf(w.x, b3, a[3]);
                    a[4]  = fmaf(w.x, b4, a[4]);
                    a[5]  = fmaf(w.y, b0, a[5]);  a[6]  = fmaf(w.y, b1, a[6]);
                    a[7]  = fmaf(w.y, b2, a[7]);  a[8]  = fmaf(w.y, b3, a[8]);
                    a[9]  = fmaf(w.y, b4, a[9]);
                    a[10] = fmaf(w.z, b0, a[10]); a[11] = fmaf(w.z, b1, a[11]);
                    a[12] = fmaf(w.z, b2, a[12]); a[13] = fmaf(w.z, b3, a[13]);
                    a[14] = fmaf(w.z, b4, a[14]);
                    a[15] = fmaf(w.w, b0, a[15]); a[16] = fmaf(w.w, b1, a[16]);
                    a[17] = fmaf(w.w, b2, a[17]); a[18] = fmaf(w.w, b3, a[18]);
                    a[19] = fmaf(w.w, b4, a[19]);
                }
                if (valid) {
                    float4* o4 = (float4*)(orow + 160 + og * 20);  // 16B aligned (640+80*og)
                    o4[0] = make_float4(a[0],  a[1],  a[2],  a[3]);
                    o4[1] = make_float4(a[4],  a[5],  a[6],  a[7]);
                    o4[2] = make_float4(a[8],  a[9],  a[10], a[11]);
                    o4[3] = make_float4(a[12], a[13], a[14], a[15]);
                    o4[4] = make_float4(a[16], a[17], a[18], a[19]);
                }
            }
        }
    }
}

// ---------------------------------------------------------------------------
extern "C" void kernel_launch(void* const* d_in, const int* in_sizes, int n_in,
                              void* d_out, int out_size) {
    const float* x  = (const float*)d_in[0];
    const float* W0 = (const float*)d_in[1];
    const float* W1 = (const float*)d_in[2];
    const float* W2 = (const float*)d_in[3];
    const int*  idx = (const int*)d_in[4];
    float* out = (float*)d_out;

    k_zero<<<1, NUM_TYPES>>>();
    k_hist<<<N_NODES / 256, 256>>>(idx);
    k_scan<<<1, 1>>>();
    k_scatter<<<N_NODES / 256, 256>>>(idx);
    k_main<<<NUM_TYPES * KBLK, 128>>>(x, W0, W1, W2, out);
}